// round 15
// baseline (speedup 1.0000x reference)
#include <cuda_runtime.h>
#include <cuda_fp16.h>
#include <math.h>
#include <stdint.h>

// ---------------- problem constants ----------------
#define B_  4
#define T_  1024
#define D_  768
#define H_  12
#define HD_ 64
#define L_  6
#define V_  50257
#define VPAD 50304
#define NPART (VPAD / 128)
#define NT  4096
#define FF  3072

// ---------------- scratch ----------------
__device__ float  g_x  [NT * D_];
__device__ float  g_nll[NT];
__device__ float2 g_nllpart[(size_t)NT * NPART];
__device__ __half g_h  [NT * D_];
__device__ __half g_q  [NT * D_];
__device__ __half g_k  [NT * D_];
__device__ __half g_vt [NT * D_];            // [B][H][HD][T]
__device__ __half g_att[NT * D_];
__device__ __half g_mlp[NT * FF];
__device__ __half g_wqkvT[L_ * 3 * D_ * D_];
__device__ __half g_wpT [L_ * D_ * D_];
__device__ __half g_w1T [L_ * FF * D_];
__device__ __half g_w2T [L_ * D_ * FF];
__device__ __half g_lmwT[(size_t)VPAD * D_];

// ---------------- helpers ----------------
__device__ __forceinline__ uint32_t smem_u32(const void* p) {
    uint32_t a;
    asm("{ .reg .u64 t; cvta.to.shared.u64 t, %1; cvt.u32.u64 %0, t; }" : "=r"(a) : "l"(p));
    return a;
}
__device__ __forceinline__ void ldm_x4(uint32_t* r, uint32_t addr) {
    asm volatile("ldmatrix.sync.aligned.m8n8.x4.shared.b16 {%0,%1,%2,%3}, [%4];"
        : "=r"(r[0]), "=r"(r[1]), "=r"(r[2]), "=r"(r[3]) : "r"(addr));
}
__device__ __forceinline__ void mma16816(float* c, const uint32_t* a, const uint32_t* b) {
    asm volatile(
        "mma.sync.aligned.m16n8k16.row.col.f32.f16.f16.f32 "
        "{%0,%1,%2,%3},{%4,%5,%6,%7},{%8,%9},{%0,%1,%2,%3};"
        : "+f"(c[0]), "+f"(c[1]), "+f"(c[2]), "+f"(c[3])
        : "r"(a[0]), "r"(a[1]), "r"(a[2]), "r"(a[3]), "r"(b[0]), "r"(b[1]));
}
__device__ __forceinline__ uint32_t pack_h2(float x, float y) {
    __half2 h = __floats2half2_rn(x, y);
    return *reinterpret_cast<uint32_t*>(&h);
}
__device__ __forceinline__ float fexp(float x) {
    x = fmaxf(x, -87.0f);
    float t = x * 1.4426950408889634f;
    float r = rintf(t);
    float f = t - r;
    float p =              1.3534550e-4f;
    p = fmaf(p, f, 1.3333558e-3f);
    p = fmaf(p, f, 9.6181291e-3f);
    p = fmaf(p, f, 5.5504109e-2f);
    p = fmaf(p, f, 2.4022651e-1f);
    p = fmaf(p, f, 6.9314718e-1f);
    p = fmaf(p, f, 1.0f);
    int i = (int)r;
    return __int_as_float(__float_as_int(p) + (i << 23));
}
#define CP_ASYNC16(dst, src) \
    asm volatile("cp.async.cg.shared.global [%0], [%1], 16;" :: "r"(dst), "l"(src) : "memory")
#define CP_COMMIT() asm volatile("cp.async.commit_group;" ::: "memory")
#define CP_WAIT(n)  asm volatile("cp.async.wait_group %0;" :: "n"(n) : "memory")

// ---------------- fp16 mma.sync GEMM: BKC=64, NSTAGE=3, single-sync mainloop ----------
// transC: 0 = row-major store; 1 = V-transpose; 2 = fused QKV routing.
#define BKC 64
#define RSTR 144     // 128B data + 16B pad per row; conflict-free (stride ≡ 16B mod 128B)
#define NSTAGE 3

template<int BN, typename CT>
__global__ __launch_bounds__(256, 2)
void gemm_h_kernel(const __half* __restrict__ A, const __half* __restrict__ Bt,
                   const float* __restrict__ bias, const float* __restrict__ R,
                   CT* __restrict__ C,
                   __half* __restrict__ Ck, __half* __restrict__ Cv,
                   float2* __restrict__ NP,
                   int M, int Nstore, int K, int lda, int ldb, int ldc,
                   long sAb, long sAh, long sBb, long sBh, long sCb, long sCh,
                   int batchH, float alpha, int act, int transC, int swapxy)
{
    extern __shared__ __align__(16) char dynsmem[];
    constexpr int ABUF  = 128 * RSTR;          // 18432
    constexpr int BBUF  = BN * RSTR;
    constexpr int BUFSZ = ABUF + BBUF;
    constexpr int NFR   = BN / 16;
    constexpr int BNP   = BN + 1;
    constexpr int NAL   = 4;                   // A 16B transfers per thread per chunk
    constexpr int NBL2  = BN / 32;             // B 16B transfers per thread per chunk

    uint32_t sbase = smem_u32(dynsmem);
    int tid = threadIdx.x;
    int lane = tid & 31, warp = tid >> 5;
    int wm = warp & 3, wn = warp >> 2;

    int z  = blockIdx.z;
    int bz = z / batchH, hz = z % batchH;
    A  += (long)bz * sAb + (long)hz * sAh;
    Bt += (long)bz * sBb + (long)hz * sBh;
    C  += (long)bz * sCb + (long)hz * sCh;
    if (R) R += (long)bz * sCb + (long)hz * sCh;

    int bxn = swapxy ? blockIdx.y : blockIdx.x;
    int bym = swapxy ? blockIdx.x : blockIdx.y;
    int m0 = bym * 128;
    int n0 = bxn * BN;

    float acc[2][NFR][4];
#pragma unroll
    for (int mt = 0; mt < 2; mt++)
#pragma unroll
        for (int nt = 0; nt < NFR; nt++)
#pragma unroll
            for (int rg = 0; rg < 4; rg++) acc[mt][nt][rg] = 0.f;

    int nchunks = K / BKC;

    auto issue = [&](int c) {
        int k0 = c * BKC;
        uint32_t ab = sbase + (c % NSTAGE) * BUFSZ;
#pragma unroll
        for (int i = 0; i < NAL; i++) {
            int s = tid + i * 256;                 // 1024 slots: row = s>>3, chunk = s&7
            uint32_t dst = ab + (uint32_t)((s >> 3) * RSTR + (s & 7) * 16);
            const __half* src = &A[(long)(m0 + (s >> 3)) * lda + k0 + (s & 7) * 8];
            CP_ASYNC16(dst, src);
        }
        uint32_t bb = ab + ABUF;
#pragma unroll
        for (int i = 0; i < NBL2; i++) {
            int s = tid + i * 256;
            uint32_t dst = bb + (uint32_t)((s >> 3) * RSTR + (s & 7) * 16);
            const __half* src = &Bt[(long)(n0 + (s >> 3)) * ldb + k0 + (s & 7) * 8];
            CP_ASYNC16(dst, src);
        }
    };

#pragma unroll
    for (int c = 0; c < NSTAGE - 1; c++) {
        if (c < nchunks) issue(c);
        CP_COMMIT();
    }

    for (int c = 0; c < nchunks; c++) {
        CP_WAIT(NSTAGE - 2);
        __syncthreads();   // publishes chunk c; also fences compute(c-1) before issue below

        int nx = c + NSTAGE - 1;
        if (nx < nchunks) issue(nx);
        CP_COMMIT();

        uint32_t abuf = sbase + (c % NSTAGE) * BUFSZ;
        uint32_t bbuf = abuf + ABUF;
#pragma unroll
        for (int ks = 0; ks < 4; ks++) {
            uint32_t af[2][4], bf[NFR][2];
#pragma unroll
            for (int mt = 0; mt < 2; mt++) {
                uint32_t addr = abuf + (uint32_t)((wm * 32 + mt * 16 + (lane & 15)) * RSTR)
                              + ks * 32 + ((lane >> 4) << 4);
                ldm_x4(af[mt], addr);
            }
#pragma unroll
            for (int p = 0; p < NFR / 2; p++) {
                uint32_t rr4[4];
                uint32_t addr = bbuf + (uint32_t)((wn * (BN / 2) + p * 16 + (lane & 7) + ((lane >> 4) << 3)) * RSTR)
                              + ks * 32 + (((lane >> 3) & 1) << 4);
                ldm_x4(rr4, addr);
                bf[2 * p][0] = rr4[0]; bf[2 * p][1] = rr4[1];
                bf[2 * p + 1][0] = rr4[2]; bf[2 * p + 1][1] = rr4[3];
            }
#pragma unroll
            for (int mt = 0; mt < 2; mt++)
#pragma unroll
                for (int nt = 0; nt < NFR; nt++)
                    mma16816(acc[mt][nt], af[mt], bf[nt]);
        }
        // no bottom sync: next iteration's top sync provides the ordering
    }
    __syncthreads();   // before epilogue reuses smem

    // ---- epilogue ----
    {
        float* ep = (float*)dynsmem;
        int qq = lane >> 2, rr = lane & 3;
#pragma unroll
        for (int mt = 0; mt < 2; mt++)
#pragma unroll
            for (int nt = 0; nt < NFR; nt++)
#pragma unroll
                for (int rg = 0; rg < 4; rg++) {
                    int row = wm * 32 + mt * 16 + qq + (rg >> 1) * 8;
                    int col = wn * (BN / 2) + nt * 8 + rr * 2 + (rg & 1);
                    int gn = n0 + col;
                    float v = acc[mt][nt][rg] * alpha;
                    if (bias && gn < Nstore) v += bias[gn];
                    if (act) v = 0.5f * v * (1.f + erff(v * 0.70710678118654752f));
                    ep[row * BNP + col] = v;
                }
        __syncthreads();

        if (transC == 0) {
            for (int idx = tid; idx < 128 * BN; idx += 256) {
                int r2 = idx / BN, c2 = idx % BN;
                int gn = n0 + c2;
                if (gn < Nstore) {
                    long gaddr = (long)(m0 + r2) * ldc + gn;
                    float v = ep[r2 * BNP + c2];
                    if (R) v += R[gaddr];
                    C[gaddr] = (CT)v;
                }
            }
            if (NP) {
                int r2 = tid >> 1, hf = tid & 1;
                const float* rowp = &ep[r2 * BNP + hf * (BN / 2)];
                int base_gn = n0 + hf * (BN / 2);
                float mloc = -1e30f;
#pragma unroll 8
                for (int c2 = 0; c2 < BN / 2; c2++) {
                    float v = (base_gn + c2 < Nstore) ? rowp[c2] : -1e30f;
                    mloc = fmaxf(mloc, v);
                }
                float sloc = 0.f;
#pragma unroll 8
                for (int c2 = 0; c2 < BN / 2; c2++) {
                    float v = (base_gn + c2 < Nstore) ? rowp[c2] : -1e30f;
                    sloc += fexp(v - mloc);
                }
                float mo = __shfl_xor_sync(0xffffffffu, mloc, 1);
                float so = __shfl_xor_sync(0xffffffffu, sloc, 1);
                float mm = fmaxf(mloc, mo);
                float ss = sloc * fexp(mloc - mm) + so * fexp(mo - mm);
                if (hf == 0)
                    NP[(long)(m0 + r2) * NPART + bxn] = make_float2(mm, ss);
            }
        } else if (transC == 1) {
            for (int idx = tid; idx < 128 * BN; idx += 256) {
                int r2 = idx & 127, c2 = idx >> 7;
                int gm = m0 + r2, gn = n0 + c2;
                int b = gm >> 10, t = gm & 1023;
                int hh = gn >> 6, hd = gn & 63;
                Cv[(((long)b * H_ + hh) * HD_ + hd) * T_ + t] = (__half)ep[r2 * BNP + c2];
            }
        } else {
            int which = n0 / D_;
            int nloc0 = n0 - which * D_;
            if (which == 0) {
                for (int idx = tid; idx < 128 * BN; idx += 256) {
                    int r2 = idx / BN, c2 = idx % BN;
                    C[(long)(m0 + r2) * D_ + nloc0 + c2] = (CT)ep[r2 * BNP + c2];
                }
            } else if (which == 1) {
                for (int idx = tid; idx < 128 * BN; idx += 256) {
                    int r2 = idx / BN, c2 = idx % BN;
                    Ck[(long)(m0 + r2) * D_ + nloc0 + c2] = (__half)ep[r2 * BNP + c2];
                }
            } else {
                for (int idx = tid; idx < 128 * BN; idx += 256) {
                    int r2 = idx & 127, c2 = idx >> 7;
                    int gm = m0 + r2;
                    int gl = nloc0 + c2;
                    int b = gm >> 10, t = gm & 1023;
                    int hh = gl >> 6, hd = gl & 63;
                    Cv[(((long)b * H_ + hh) * HD_ + hd) * T_ + t] = (__half)ep[r2 * BNP + c2];
                }
            }
        }
    }
}

// ---------------- flash attention ----------------
#define FRS 144
#define FQ_BYTES  (128 * FRS)
#define FKV_BYTES (64 * FRS)
#define FSTAGE    (2 * FKV_BYTES)
#define FSMEM     (FQ_BYTES + 2 * FSTAGE)

__global__ __launch_bounds__(256, 1)
void flash_kernel(const __half* __restrict__ Qg, const __half* __restrict__ Kg,
                  const __half* __restrict__ Vt, __half* __restrict__ Og)
{
    extern __shared__ __align__(16) char fsm[];
    uint32_t sbase = smem_u32(fsm);
    int tid = threadIdx.x, lane = tid & 31, w = tid >> 5;
    int qq = lane >> 2, rr = lane & 3;

    int qi = blockIdx.x, bh = blockIdx.y;
    int b = bh / H_, h = bh % H_;
    int q0 = qi * 128;

    const __half* qptr = Qg + ((long)b * T_ + q0) * D_ + h * HD_;
    const __half* kptr = Kg + (long)b * T_ * D_ + h * HD_;
    const __half* vptr = Vt + (long)bh * HD_ * T_;

    uint32_t qb = sbase;

    {
#pragma unroll
        for (int i = 0; i < 4; i++) {
            int s = tid + i * 256;
            uint32_t dst = qb + (uint32_t)((s >> 3) * FRS + (s & 7) * 16);
            CP_ASYNC16(dst, qptr + (long)(s >> 3) * D_ + (s & 7) * 8);
        }
        CP_COMMIT();
    }

    int nkv = 2 * qi + 2;

    auto issue_kv = [&](int j) {
        uint32_t kb = sbase + FQ_BYTES + (j & 1) * FSTAGE;
        uint32_t vb = kb + FKV_BYTES;
        int j0 = j * 64;
#pragma unroll
        for (int i = 0; i < 2; i++) {
            int s = tid + i * 256;
            int row = s >> 3, c16 = s & 7;
            CP_ASYNC16(kb + (uint32_t)(row * FRS + c16 * 16),
                       kptr + (long)(j0 + row) * D_ + c16 * 8);
            CP_ASYNC16(vb + (uint32_t)(row * FRS + c16 * 16),
                       vptr + (long)row * T_ + j0 + c16 * 8);
        }
    };

    issue_kv(0);
    CP_COMMIT();

    float m0 = -1e30f, m1 = -1e30f, l0 = 0.f, l1 = 0.f;
    float o[8][4];
#pragma unroll
    for (int nt = 0; nt < 8; nt++)
#pragma unroll
        for (int e = 0; e < 4; e++) o[nt][e] = 0.f;

    uint32_t aq[4][4];

    for (int j = 0; j < nkv; j++) {
        __syncthreads();
        if (j + 1 < nkv) issue_kv(j + 1);
        CP_COMMIT();
        CP_WAIT(1);
        __syncthreads();

        if (j == 0) {
#pragma unroll
            for (int ks = 0; ks < 4; ks++) {
                uint32_t addr = qb + (uint32_t)((w * 16 + (lane & 15)) * FRS)
                              + ks * 32 + ((lane >> 4) << 4);
                ldm_x4(aq[ks], addr);
            }
        }

        uint32_t kb = sbase + FQ_BYTES + (j & 1) * FSTAGE;
        uint32_t vb = kb + FKV_BYTES;

        float sacc[8][4];
#pragma unroll
        for (int nt = 0; nt < 8; nt++)
#pragma unroll
            for (int e = 0; e < 4; e++) sacc[nt][e] = 0.f;

#pragma unroll
        for (int ks = 0; ks < 4; ks++) {
            uint32_t bf[8][2];
#pragma unroll
            for (int p = 0; p < 4; p++) {
                uint32_t r4[4];
                uint32_t addr = kb + (uint32_t)((p * 16 + (lane & 7) + ((lane >> 4) << 3)) * FRS)
                              + ks * 32 + (((lane >> 3) & 1) << 4);
                ldm_x4(r4, addr);
                bf[2 * p][0] = r4[0]; bf[2 * p][1] = r4[1];
                bf[2 * p + 1][0] = r4[2]; bf[2 * p + 1][1] = r4[3];
            }
#pragma unroll
            for (int nt = 0; nt < 8; nt++)
                mma16816(sacc[nt], aq[ks], bf[nt]);
        }

        int j0 = j * 64;
        int rowg0 = q0 + w * 16 + qq;
        int rowg1 = rowg0 + 8;
        bool needmask = (j >= nkv - 2);

        float rm0 = -1e30f, rm1 = -1e30f;
#pragma unroll
        for (int nt = 0; nt < 8; nt++) {
            int cb = j0 + nt * 8 + rr * 2;
            float s0 = sacc[nt][0] * 0.125f;
            float s1 = sacc[nt][1] * 0.125f;
            float s2 = sacc[nt][2] * 0.125f;
            float s3 = sacc[nt][3] * 0.125f;
            if (needmask) {
                if (cb     > rowg0) s0 = -1e30f;
                if (cb + 1 > rowg0) s1 = -1e30f;
                if (cb     > rowg1) s2 = -1e30f;
                if (cb + 1 > rowg1) s3 = -1e30f;
            }
            sacc[nt][0] = s0; sacc[nt][1] = s1; sacc[nt][2] = s2; sacc[nt][3] = s3;
            rm0 = fmaxf(rm0, fmaxf(s0, s1));
            rm1 = fmaxf(rm1, fmaxf(s2, s3));
        }
#pragma unroll
        for (int od = 1; od <= 2; od <<= 1) {
            rm0 = fmaxf(rm0, __shfl_xor_sync(0xffffffffu, rm0, od));
            rm1 = fmaxf(rm1, __shfl_xor_sync(0xffffffffu, rm1, od));
        }
        float mn0 = fmaxf(m0, rm0), mn1 = fmaxf(m1, rm1);
        float c0 = __expf(m0 - mn0), c1 = __expf(m1 - mn1);

        float rs0 = 0.f, rs1 = 0.f;
#pragma unroll
        for (int nt = 0; nt < 8; nt++) {
            float p0 = __expf(sacc[nt][0] - mn0);
            float p1 = __expf(sacc[nt][1] - mn0);
            float p2 = __expf(sacc[nt][2] - mn1);
            float p3 = __expf(sacc[nt][3] - mn1);
            sacc[nt][0] = p0; sacc[nt][1] = p1; sacc[nt][2] = p2; sacc[nt][3] = p3;
            rs0 += p0 + p1; rs1 += p2 + p3;
        }
#pragma unroll
        for (int od = 1; od <= 2; od <<= 1) {
            rs0 += __shfl_xor_sync(0xffffffffu, rs0, od);
            rs1 += __shfl_xor_sync(0xffffffffu, rs1, od);
        }
        l0 = l0 * c0 + rs0;
        l1 = l1 * c1 + rs1;
        m0 = mn0; m1 = mn1;

#pragma unroll
        for (int nt = 0; nt < 8; nt++) {
            o[nt][0] *= c0; o[nt][1] *= c0;
            o[nt][2] *= c1; o[nt][3] *= c1;
        }

        uint32_t ap[4][4];
#pragma unroll
        for (int ks2 = 0; ks2 < 4; ks2++) {
            ap[ks2][0] = pack_h2(sacc[2 * ks2][0],     sacc[2 * ks2][1]);
            ap[ks2][1] = pack_h2(sacc[2 * ks2][2],     sacc[2 * ks2][3]);
            ap[ks2][2] = pack_h2(sacc[2 * ks2 + 1][0], sacc[2 * ks2 + 1][1]);
            ap[ks2][3] = pack_h2(sacc[2 * ks2 + 1][2], sacc[2 * ks2 + 1][3]);
        }

#pragma unroll
        for (int ks2 = 0; ks2 < 4; ks2++) {
            uint32_t bf[8][2];
#pragma unroll
            for (int p = 0; p < 4; p++) {
                uint32_t r4[4];
                uint32_t addr = vb + (uint32_t)((p * 16 + (lane & 7) + ((lane >> 4) << 3)) * FRS)
                              + ks2 * 32 + (((lane >> 3) & 1) << 4);
                ldm_x4(r4, addr);
                bf[2 * p][0] = r4[0]; bf[2 * p][1] = r4[1];
                bf[2 * p + 1][0] = r4[2]; bf[2 * p + 1][1] = r4[3];
            }
#pragma unroll
            for (int nt = 0; nt < 8; nt++)
                mma16816(o[nt], ap[ks2], bf[nt]);
        }
    }

    float inv0 = 1.f / l0, inv1 = 1.f / l1;
    long obase = ((long)b * T_ + q0 + w * 16) * D_ + h * HD_;
#pragma unroll
    for (int nt = 0; nt < 8; nt++) {
        int col = nt * 8 + rr * 2;
        *(__half2*)&Og[obase + (long)qq * D_ + col] =
            __floats2half2_rn(o[nt][0] * inv0, o[nt][1] * inv0);
        *(__half2*)&Og[obase + (long)(qq + 8) * D_ + col] =
            __floats2half2_rn(o[nt][2] * inv1, o[nt][3] * inv1);
    }
}

// ---------------- single transpose ----------------
__global__ void transpose_kernel(const float* __restrict__ in, __half* __restrict__ out,
                                 int Kd, int Nd, int Nout, long sIn, long sOut)
{
    __shared__ float t[32][33];
    int zz = blockIdx.z;
    in  += (long)zz * sIn;
    out += (long)zz * sOut;
    int n = blockIdx.x * 32 + threadIdx.x;
#pragma unroll
    for (int j = 0; j < 4; j++) {
        int k = blockIdx.y * 32 + threadIdx.y + j * 8;
        t[threadIdx.y + j * 8][threadIdx.x] = (n < Nd && k < Kd) ? in[(long)k * Nd + n] : 0.f;
    }
    __syncthreads();
#pragma unroll
    for (int j = 0; j < 4; j++) {
        int n2 = blockIdx.x * 32 + threadIdx.y + j * 8;
        int k2 = blockIdx.y * 32 + threadIdx.x;
        if (n2 < Nout && k2 < Kd) out[(long)n2 * Kd + k2] = __float2half(t[threadIdx.x][threadIdx.y + j * 8]);
    }
}

// ---------------- merged 4x D×D transpose ----------------
__global__ void transpose4_kernel(const float* __restrict__ wq, const float* __restrict__ wk,
                                  const float* __restrict__ wv, const float* __restrict__ wp,
                                  __half* __restrict__ qkvT, __half* __restrict__ wpT)
{
    __shared__ float t[32][33];
    int zz = blockIdx.z;
    int which = zz & 3, l = zz >> 2;
    const float* in;
    __half* out;
    if (which == 0)      { in = wq + (long)l * D_ * D_; out = qkvT + (long)l * 3 * D_ * D_; }
    else if (which == 1) { in = wk + (long)l * D_ * D_; out = qkvT + (long)l * 3 * D_ * D_ + (long)D_ * D_; }
    else if (which == 2) { in = wv + (long)l * D_ * D_; out = qkvT + (long)l * 3 * D_ * D_ + 2L * D_ * D_; }
    else                 { in = wp + (long)l * D_ * D_; out = wpT  + (long)l * D_ * D_; }

    int n = blockIdx.x * 32 + threadIdx.x;
#pragma unroll
    for (int j = 0; j < 4; j++) {
        int k = blockIdx.y * 32 + threadIdx.y + j * 8;
        t[threadIdx.y + j * 8][threadIdx.x] = in[(long)k * D_ + n];
    }
    __syncthreads();
#pragma unroll
    for (int j = 0; j < 4; j++) {
        int n2 = blockIdx.x * 32 + threadIdx.y + j * 8;
        int k2 = blockIdx.y * 32 + threadIdx.x;
        out[(long)n2 * D_ + k2] = __float2half(t[threadIdx.x][threadIdx.y + j * 8]);
    }
}

// ---------------- embedding ----------------
__global__ void embed_kernel(const int* __restrict__ idx, const float* __restrict__ tok,
                             const float* __restrict__ pos, float* __restrict__ x)
{
    long i = (long)blockIdx.x * 256 + threadIdx.x;
    if (i >= (long)NT * D_) return;
    int d = (int)(i % D_);
    long row = i / D_;
    int t = (int)(row % T_);
    x[i] = tok[(long)idx[row] * D_ + d] + pos[(long)t * D_ + d];
}

// ---------------- layernorm ----------------
__global__ void layernorm_kernel(const float* __restrict__ x, const float* __restrict__ w,
                                 const float* __restrict__ b, __half* __restrict__ y)
{
    int r = blockIdx.x;
    const float* xr = x + (long)r * D_;
    __half* yr = y + (long)r * D_;
    __shared__ float s1[256], s2[256];
    int tid = threadIdx.x;
    float a = 0.f, sq = 0.f;
    for (int i = tid; i < D_; i += 256) { float v = xr[i]; a += v; sq += v * v; }
    s1[tid] = a; s2[tid] = sq; __syncthreads();
    for (int s = 128; s > 0; s >>= 1) {
        if (tid < s) { s1[tid] += s1[tid + s]; s2[tid] += s2[tid + s]; }
        __syncthreads();
    }
    float mu = s1[0] * (1.f / D_);
    float var = s2[0] * (1.f / D_) - mu * mu;
    float rstd = rsqrtf(var + 1e-5f);
    for (int i = tid; i < D_; i += 256)
        yr[i] = __float2half((xr[i] - mu) * rstd * w[i] + b[i]);
}

// ---------------- NLL from partials ----------------
__global__ void nll_from_partials(const float2* __restrict__ NP, const float* __restrict__ logits,
                                  const int* __restrict__ targets, float* __restrict__ nll)
{
    int row = blockIdx.x;
    const float2* p = NP + (long)row * NPART;
    int tid = threadIdx.x;
    float m = -1e30f, s = 0.f;
    for (int i = tid; i < NPART; i += 256) {
        float2 v = p[i];
        float mn = fmaxf(m, v.x);
        s = s * fexp(m - mn) + v.y * fexp(v.x - mn);
        m = mn;
    }
#pragma unroll
    for (int o = 16; o; o >>= 1) {
        float mo = __shfl_xor_sync(0xffffffffu, m, o);
        float so = __shfl_xor_sync(0xffffffffu, s, o);
        float mn = fmaxf(m, mo);
        s = s * fexp(m - mn) + so * fexp(mo - mn);
        m = mn;
    }
    __shared__ float sm[8], ssh[8];
    if ((tid & 31) == 0) { sm[tid >> 5] = m; ssh[tid >> 5] = s; }
    __syncthreads();
    if (tid == 0) {
        m = sm[0]; s = ssh[0];
#pragma unroll
        for (int i = 1; i < 8; i++) {
            float mn = fmaxf(m, sm[i]);
            s = s * fexp(m - mn) + ssh[i] * fexp(sm[i] - mn);
            m = mn;
        }
        nll[row] = m + logf(s) - logits[(long)row * V_ + targets[row]];
    }
}

__global__ void loss_reduce_kernel(const float* __restrict__ nll, float* __restrict__ out)
{
    __shared__ float red[256];
    int tid = threadIdx.x;
    float a = 0.f;
    for (int i = tid; i < NT; i += 256) a += nll[i];
    red[tid] = a; __syncthreads();
    for (int s = 128; s > 0; s >>= 1) { if (tid < s) red[tid] += red[tid + s]; __syncthreads(); }
    if (tid == 0) out[0] = red[0] * (1.f / NT);
}

// ---------------- host ----------------
#define SMEM128 110592   // 3 stages * (128+128)*144; epilogue 66048 fits

extern "C" void kernel_launch(void* const* d_in, const int* in_sizes, int n_in,
                              void* d_out, int out_size)
{
    const float* tok_emb = (const float*)d_in[0];
    const float* pos_emb = (const float*)d_in[1];
    const float* ln1_w   = (const float*)d_in[2];
    const float* ln1_b   = (const float*)d_in[3];
    const float* ln2_w   = (const float*)d_in[4];
    const float* ln2_b   = (const float*)d_in[5];
    const float* wq      = (const float*)d_in[6];
    const float* wk      = (const float*)d_in[7];
    const float* wv      = (const float*)d_in[8];
    const float* wproj   = (const float*)d_in[9];
    const float* bproj   = (const float*)d_in[10];
    const float* w1      = (const float*)d_in[11];
    const float* b1      = (const float*)d_in[12];
    const float* w2      = (const float*)d_in[13];
    const float* b2      = (const float*)d_in[14];
    const float* lnf_w   = (const float*)d_in[15];
    const float* lnf_b   = (const float*)d_in[16];
    const float* lm_w    = (const float*)d_in[17];
    const float* lm_b    = (const float*)d_in[18];
    const int*   indexp  = (const int*)d_in[19];
    const int*   targets = (const int*)d_in[20];

    float* out = (float*)d_out;

    cudaFuncSetAttribute(gemm_h_kernel<128, float>,  cudaFuncAttributeMaxDynamicSharedMemorySize, SMEM128);
    cudaFuncSetAttribute(gemm_h_kernel<128, __half>, cudaFuncAttributeMaxDynamicSharedMemorySize, SMEM128);
    cudaFuncSetAttribute(flash_kernel, cudaFuncAttributeMaxDynamicSharedMemorySize, FSMEM);

    float *x, *nll;
    float2* npart;
    __half *h, *q, *kh, *vt, *att, *mlp;
    __half *qkvT, *wpT, *w1T, *w2T, *lmwT;
    cudaGetSymbolAddress((void**)&x,      g_x);
    cudaGetSymbolAddress((void**)&nll,    g_nll);
    cudaGetSymbolAddress((void**)&npart,  g_nllpart);
    cudaGetSymbolAddress((void**)&h,      g_h);
    cudaGetSymbolAddress((void**)&q,      g_q);
    cudaGetSymbolAddress((void**)&kh,     g_k);
    cudaGetSymbolAddress((void**)&vt,     g_vt);
    cudaGetSymbolAddress((void**)&att,    g_att);
    cudaGetSymbolAddress((void**)&mlp,    g_mlp);
    cudaGetSymbolAddress((void**)&qkvT,   g_wqkvT);
    cudaGetSymbolAddress((void**)&wpT,    g_wpT);
    cudaGetSymbolAddress((void**)&w1T,    g_w1T);
    cudaGetSymbolAddress((void**)&w2T,    g_w2T);
    cudaGetSymbolAddress((void**)&lmwT,   g_lmwT);

    dim3 tb(32, 8);

    {
        long total = (long)NT * D_;
        embed_kernel<<<(int)((total + 255) / 256), 256>>>(indexp, tok_emb, pos_emb, x);

        dim3 g4(D_ / 32, D_ / 32, 4 * L_);
        transpose4_kernel<<<g4, tb>>>(wq, wk, wv, wproj, qkvT, wpT);
        dim3 g1(FF / 32, D_ / 32, L_);
        transpose_kernel<<<g1, tb>>>(w1, w1T, D_, FF, FF, (long)D_ * FF, (long)FF * D_);
        dim3 g2(D_ / 32, FF / 32, L_);
        transpose_kernel<<<g2, tb>>>(w2, w2T, FF, D_, D_, (long)FF * D_, (long)D_ * FF);
    }

    for (int l = 0; l < L_; l++) {
        const __half* qkvT_l = qkvT + (long)l * 3 * D_ * D_;
        const __half* wpT_l  = wpT + (long)l * D_ * D_;
        const float*  bp_l   = bproj + (long)l * D_;
        const __half* w1T_l  = w1T + (long)l * FF * D_;
        const float*  b1_l   = b1 + (long)l * FF;
        const __half* w2T_l  = w2T + (long)l * D_ * FF;
        const float*  b2_l   = b2 + (long)l * D_;

        layernorm_kernel<<<NT, 256>>>(x, ln1_w + (long)l * D_, ln1_b + (long)l * D_, h);

        gemm_h_kernel<128, __half><<<dim3(3 * D_ / 128, NT / 128, 1), 256, SMEM128>>>(
            h, qkvT_l, nullptr, nullptr, q, kh, vt, nullptr, NT, 3 * D_, D_, D_, D_, D_,
            0, 0, 0, 0, 0, 0, 1, 1.f, 0, 2, 0);

        flash_kernel<<<dim3(T_ / 128, B_ * H_), 256, FSMEM>>>(q, kh, vt, att);

        gemm_h_kernel<128, float><<<dim3(D_ / 128, NT / 128, 1), 256, SMEM128>>>(
            att, wpT_l, bp_l, x, x, nullptr, nullptr, nullptr, NT, D_, D_, D_, D_, D_,
            0, 0, 0, 0, 0, 0, 1, 1.f, 0, 0, 0);

        layernorm_kernel<<<NT, 256>>>(x, ln2_w + (long)l * D_, ln2_b + (long)l * D_, h);

        gemm_h_kernel<128, __half><<<dim3(FF / 128, NT / 128, 1), 256, SMEM128>>>(
            h, w1T_l, b1_l, nullptr, mlp, nullptr, nullptr, nullptr, NT, FF, D_, D_, D_, FF,
            0, 0, 0, 0, 0, 0, 1, 1.f, 1, 0, 0);

        gemm_h_kernel<128, float><<<dim3(D_ / 128, NT / 128, 1), 256, SMEM128>>>(
            mlp, w2T_l, b2_l, x, x, nullptr, nullptr, nullptr, NT, D_, FF, FF, FF, D_,
            0, 0, 0, 0, 0, 0, 1, 1.f, 0, 0, 0);
    }

    layernorm_kernel<<<NT, 256>>>(x, lnf_w, lnf_b, h);

    long logits_elems = (long)NT * V_;
    if ((long)out_size >= logits_elems) {
        dim3 g3(VPAD / 32, D_ / 32, 1);
        transpose_kernel<<<g3, tb>>>(lm_w, lmwT, D_, V_, VPAD, 0, 0);

        gemm_h_kernel<128, float><<<dim3(NT / 128, VPAD / 128, 1), 256, SMEM128>>>(
            h, lmwT, lm_b, nullptr, out, nullptr, nullptr, npart, NT, V_, D_, D_, D_, V_,
            0, 0, 0, 0, 0, 0, 1, 1.f, 0, 0, 1);

        nll_from_partials<<<NT, 256>>>(npart, out, targets, nll);
        if ((long)out_size >= logits_elems + 1) {
            loss_reduce_kernel<<<1, 256>>>(nll, out + logits_elems);
        }
    }
}

// round 17
// speedup vs baseline: 1.0757x; 1.0757x over previous
#include <cuda_runtime.h>
#include <cuda_fp16.h>
#include <math.h>
#include <stdint.h>

// ---------------- problem constants ----------------
#define B_  4
#define T_  1024
#define D_  768
#define H_  12
#define HD_ 64
#define L_  6
#define V_  50257
#define VPAD 50304
#define NPART (VPAD / 128)
#define NT  4096
#define FF  3072

// ---------------- scratch ----------------
__device__ float  g_x  [NT * D_];
__device__ float  g_nll[NT];
__device__ float2 g_nllpart[(size_t)NT * NPART];
__device__ __half g_h  [NT * D_];
__device__ __half g_q  [NT * D_];
__device__ __half g_k  [NT * D_];
__device__ __half g_vt [NT * D_];            // [B][H][HD][T]
__device__ __half g_att[NT * D_];
__device__ __half g_mlp[NT * FF];
__device__ __half g_wqkvT[L_ * 3 * D_ * D_];
__device__ __half g_wpT [L_ * D_ * D_];
__device__ __half g_w1T [L_ * FF * D_];
__device__ __half g_w2T [L_ * D_ * FF];
__device__ __half g_lmwT[(size_t)VPAD * D_];

// ---------------- helpers ----------------
__device__ __forceinline__ uint32_t smem_u32(const void* p) {
    uint32_t a;
    asm("{ .reg .u64 t; cvta.to.shared.u64 t, %1; cvt.u32.u64 %0, t; }" : "=r"(a) : "l"(p));
    return a;
}
__device__ __forceinline__ void ldm_x4(uint32_t* r, uint32_t addr) {
    asm volatile("ldmatrix.sync.aligned.m8n8.x4.shared.b16 {%0,%1,%2,%3}, [%4];"
        : "=r"(r[0]), "=r"(r[1]), "=r"(r[2]), "=r"(r[3]) : "r"(addr));
}
__device__ __forceinline__ void mma16816(float* c, const uint32_t* a, const uint32_t* b) {
    asm volatile(
        "mma.sync.aligned.m16n8k16.row.col.f32.f16.f16.f32 "
        "{%0,%1,%2,%3},{%4,%5,%6,%7},{%8,%9},{%0,%1,%2,%3};"
        : "+f"(c[0]), "+f"(c[1]), "+f"(c[2]), "+f"(c[3])
        : "r"(a[0]), "r"(a[1]), "r"(a[2]), "r"(a[3]), "r"(b[0]), "r"(b[1]));
}
__device__ __forceinline__ uint32_t pack_h2(float x, float y) {
    __half2 h = __floats2half2_rn(x, y);
    return *reinterpret_cast<uint32_t*>(&h);
}
__device__ __forceinline__ float fexp(float x) {
    x = fmaxf(x, -87.0f);
    float t = x * 1.4426950408889634f;
    float r = rintf(t);
    float f = t - r;
    float p =              1.3534550e-4f;
    p = fmaf(p, f, 1.3333558e-3f);
    p = fmaf(p, f, 9.6181291e-3f);
    p = fmaf(p, f, 5.5504109e-2f);
    p = fmaf(p, f, 2.4022651e-1f);
    p = fmaf(p, f, 6.9314718e-1f);
    p = fmaf(p, f, 1.0f);
    int i = (int)r;
    return __int_as_float(__float_as_int(p) + (i << 23));
}
#define CP_ASYNC16(dst, src) \
    asm volatile("cp.async.cg.shared.global [%0], [%1], 16;" :: "r"(dst), "l"(src) : "memory")
#define CP_COMMIT() asm volatile("cp.async.commit_group;" ::: "memory")
#define CP_WAIT(n)  asm volatile("cp.async.wait_group %0;" :: "n"(n) : "memory")

// ---------------- fp16 mma.sync GEMM: BKC=32, NSTAGE=4, single-sync mainloop ----------
// transC: 0 = row-major store; 1 = V-transpose; 2 = fused QKV routing.
#define BKC 32
#define RSTR 80
#define NSTAGE 4

template<int BN, typename CT>
__global__ __launch_bounds__(256, 2)
void gemm_h_kernel(const __half* __restrict__ A, const __half* __restrict__ Bt,
                   const float* __restrict__ bias, const float* __restrict__ R,
                   CT* __restrict__ C,
                   __half* __restrict__ Ck, __half* __restrict__ Cv,
                   float2* __restrict__ NP,
                   int M, int Nstore, int K, int lda, int ldb, int ldc,
                   long sAb, long sAh, long sBb, long sBh, long sCb, long sCh,
                   int batchH, float alpha, int act, int transC, int swapxy)
{
    extern __shared__ __align__(16) char dynsmem[];
    constexpr int ABUF  = 128 * RSTR;
    constexpr int BBUF  = BN * RSTR;
    constexpr int BUFSZ = ABUF + BBUF;
    constexpr int NFR   = BN / 16;
    constexpr int NBL   = BN / 64;
    constexpr int BNP   = BN + 1;

    uint32_t sbase = smem_u32(dynsmem);
    int tid = threadIdx.x;
    int lane = tid & 31, warp = tid >> 5;
    int wm = warp & 3, wn = warp >> 2;

    int z  = blockIdx.z;
    int bz = z / batchH, hz = z % batchH;
    A  += (long)bz * sAb + (long)hz * sAh;
    Bt += (long)bz * sBb + (long)hz * sBh;
    C  += (long)bz * sCb + (long)hz * sCh;
    if (R) R += (long)bz * sCb + (long)hz * sCh;

    int bxn = swapxy ? blockIdx.y : blockIdx.x;
    int bym = swapxy ? blockIdx.x : blockIdx.y;
    int m0 = bym * 128;
    int n0 = bxn * BN;

    float acc[2][NFR][4];
#pragma unroll
    for (int mt = 0; mt < 2; mt++)
#pragma unroll
        for (int nt = 0; nt < NFR; nt++)
#pragma unroll
            for (int rg = 0; rg < 4; rg++) acc[mt][nt][rg] = 0.f;

    int nchunks = K / BKC;

    auto issue = [&](int c) {
        int k0 = c * BKC;
        uint32_t ab = sbase + (c % NSTAGE) * BUFSZ;
#pragma unroll
        for (int i = 0; i < 2; i++) {
            int s = tid + i * 256;
            uint32_t dst = ab + (uint32_t)((s >> 2) * RSTR + (s & 3) * 16);
            const __half* src = &A[(long)(m0 + (s >> 2)) * lda + k0 + (s & 3) * 8];
            CP_ASYNC16(dst, src);
        }
        uint32_t bb = ab + ABUF;
#pragma unroll
        for (int i = 0; i < NBL; i++) {
            int s = tid + i * 256;
            uint32_t dst = bb + (uint32_t)((s >> 2) * RSTR + (s & 3) * 16);
            const __half* src = &Bt[(long)(n0 + (s >> 2)) * ldb + k0 + (s & 3) * 8];
            CP_ASYNC16(dst, src);
        }
    };

#pragma unroll
    for (int c = 0; c < NSTAGE - 1; c++) {
        if (c < nchunks) issue(c);
        CP_COMMIT();
    }

    for (int c = 0; c < nchunks; c++) {
        CP_WAIT(NSTAGE - 2);
        __syncthreads();   // publishes chunk c; orders compute(c-1) before issue below

        int nx = c + NSTAGE - 1;
        if (nx < nchunks) issue(nx);
        CP_COMMIT();

        uint32_t abuf = sbase + (c % NSTAGE) * BUFSZ;
        uint32_t bbuf = abuf + ABUF;
#pragma unroll
        for (int ks = 0; ks < 2; ks++) {
            uint32_t af[2][4], bf[NFR][2];
#pragma unroll
            for (int mt = 0; mt < 2; mt++) {
                uint32_t addr = abuf + (uint32_t)((wm * 32 + mt * 16 + (lane & 15)) * RSTR)
                              + ks * 32 + ((lane >> 4) << 4);
                ldm_x4(af[mt], addr);
            }
#pragma unroll
            for (int p = 0; p < NFR / 2; p++) {
                uint32_t rr4[4];
                uint32_t addr = bbuf + (uint32_t)((wn * (BN / 2) + p * 16 + (lane & 7) + ((lane >> 4) << 3)) * RSTR)
                              + ks * 32 + (((lane >> 3) & 1) << 4);
                ldm_x4(rr4, addr);
                bf[2 * p][0] = rr4[0]; bf[2 * p][1] = rr4[1];
                bf[2 * p + 1][0] = rr4[2]; bf[2 * p + 1][1] = rr4[3];
            }
#pragma unroll
            for (int mt = 0; mt < 2; mt++)
#pragma unroll
                for (int nt = 0; nt < NFR; nt++)
                    mma16816(acc[mt][nt], af[mt], bf[nt]);
        }
        // no bottom sync: next iteration's top sync provides the ordering
    }
    __syncthreads();   // before epilogue reuses smem

    // ---- epilogue ----
    {
        float* ep = (float*)dynsmem;
        int qq = lane >> 2, rr = lane & 3;
#pragma unroll
        for (int mt = 0; mt < 2; mt++)
#pragma unroll
            for (int nt = 0; nt < NFR; nt++)
#pragma unroll
                for (int rg = 0; rg < 4; rg++) {
                    int row = wm * 32 + mt * 16 + qq + (rg >> 1) * 8;
                    int col = wn * (BN / 2) + nt * 8 + rr * 2 + (rg & 1);
                    int gn = n0 + col;
                    float v = acc[mt][nt][rg] * alpha;
                    if (bias && gn < Nstore) v += bias[gn];
                    if (act) v = 0.5f * v * (1.f + erff(v * 0.70710678118654752f));
                    ep[row * BNP + col] = v;
                }
        __syncthreads();

        if (transC == 0) {
            for (int idx = tid; idx < 128 * BN; idx += 256) {
                int r2 = idx / BN, c2 = idx % BN;
                int gn = n0 + c2;
                if (gn < Nstore) {
                    long gaddr = (long)(m0 + r2) * ldc + gn;
                    float v = ep[r2 * BNP + c2];
                    if (R) v += R[gaddr];
                    C[gaddr] = (CT)v;
                }
            }
            if (NP) {
                int r2 = tid >> 1, hf = tid & 1;
                const float* rowp = &ep[r2 * BNP + hf * (BN / 2)];
                int base_gn = n0 + hf * (BN / 2);
                float mloc = -1e30f;
#pragma unroll 8
                for (int c2 = 0; c2 < BN / 2; c2++) {
                    float v = (base_gn + c2 < Nstore) ? rowp[c2] : -1e30f;
                    mloc = fmaxf(mloc, v);
                }
                float sloc = 0.f;
#pragma unroll 8
                for (int c2 = 0; c2 < BN / 2; c2++) {
                    float v = (base_gn + c2 < Nstore) ? rowp[c2] : -1e30f;
                    sloc += fexp(v - mloc);
                }
                float mo = __shfl_xor_sync(0xffffffffu, mloc, 1);
                float so = __shfl_xor_sync(0xffffffffu, sloc, 1);
                float mm = fmaxf(mloc, mo);
                float ss = sloc * fexp(mloc - mm) + so * fexp(mo - mm);
                if (hf == 0)
                    NP[(long)(m0 + r2) * NPART + bxn] = make_float2(mm, ss);
            }
        } else if (transC == 1) {
            for (int idx = tid; idx < 128 * BN; idx += 256) {
                int r2 = idx & 127, c2 = idx >> 7;
                int gm = m0 + r2, gn = n0 + c2;
                int b = gm >> 10, t = gm & 1023;
                int hh = gn >> 6, hd = gn & 63;
                Cv[(((long)b * H_ + hh) * HD_ + hd) * T_ + t] = (__half)ep[r2 * BNP + c2];
            }
        } else {
            int which = n0 / D_;
            int nloc0 = n0 - which * D_;
            if (which == 0) {
                for (int idx = tid; idx < 128 * BN; idx += 256) {
                    int r2 = idx / BN, c2 = idx % BN;
                    C[(long)(m0 + r2) * D_ + nloc0 + c2] = (CT)ep[r2 * BNP + c2];
                }
            } else if (which == 1) {
                for (int idx = tid; idx < 128 * BN; idx += 256) {
                    int r2 = idx / BN, c2 = idx % BN;
                    Ck[(long)(m0 + r2) * D_ + nloc0 + c2] = (__half)ep[r2 * BNP + c2];
                }
            } else {
                for (int idx = tid; idx < 128 * BN; idx += 256) {
                    int r2 = idx & 127, c2 = idx >> 7;
                    int gm = m0 + r2;
                    int gl = nloc0 + c2;
                    int b = gm >> 10, t = gm & 1023;
                    int hh = gl >> 6, hd = gl & 63;
                    Cv[(((long)b * H_ + hh) * HD_ + hd) * T_ + t] = (__half)ep[r2 * BNP + c2];
                }
            }
        }
    }
}

// ---------------- flash attention (heavy-first scheduling) ----------------
#define FRS 144
#define FQ_BYTES  (128 * FRS)
#define FKV_BYTES (64 * FRS)
#define FSTAGE    (2 * FKV_BYTES)
#define FSMEM     (FQ_BYTES + 2 * FSTAGE)

__global__ __launch_bounds__(256, 1)
void flash_kernel(const __half* __restrict__ Qg, const __half* __restrict__ Kg,
                  const __half* __restrict__ Vt, __half* __restrict__ Og)
{
    extern __shared__ __align__(16) char fsm[];
    uint32_t sbase = smem_u32(fsm);
    int tid = threadIdx.x, lane = tid & 31, w = tid >> 5;
    int qq = lane >> 2, rr = lane & 3;

    // heavy tiles (large qi -> most kv iterations) scheduled first
    int qi = (T_ / 128) - 1 - blockIdx.x;
    int bh = blockIdx.y;
    int b = bh / H_, h = bh % H_;
    int q0 = qi * 128;

    const __half* qptr = Qg + ((long)b * T_ + q0) * D_ + h * HD_;
    const __half* kptr = Kg + (long)b * T_ * D_ + h * HD_;
    const __half* vptr = Vt + (long)bh * HD_ * T_;

    uint32_t qb = sbase;

    {
#pragma unroll
        for (int i = 0; i < 4; i++) {
            int s = tid + i * 256;
            uint32_t dst = qb + (uint32_t)((s >> 3) * FRS + (s & 7) * 16);
            CP_ASYNC16(dst, qptr + (long)(s >> 3) * D_ + (s & 7) * 8);
        }
        CP_COMMIT();
    }

    int nkv = 2 * qi + 2;

    auto issue_kv = [&](int j) {
        uint32_t kb = sbase + FQ_BYTES + (j & 1) * FSTAGE;
        uint32_t vb = kb + FKV_BYTES;
        int j0 = j * 64;
#pragma unroll
        for (int i = 0; i < 2; i++) {
            int s = tid + i * 256;
            int row = s >> 3, c16 = s & 7;
            CP_ASYNC16(kb + (uint32_t)(row * FRS + c16 * 16),
                       kptr + (long)(j0 + row) * D_ + c16 * 8);
            CP_ASYNC16(vb + (uint32_t)(row * FRS + c16 * 16),
                       vptr + (long)row * T_ + j0 + c16 * 8);
        }
    };

    issue_kv(0);
    CP_COMMIT();

    float m0 = -1e30f, m1 = -1e30f, l0 = 0.f, l1 = 0.f;
    float o[8][4];
#pragma unroll
    for (int nt = 0; nt < 8; nt++)
#pragma unroll
        for (int e = 0; e < 4; e++) o[nt][e] = 0.f;

    uint32_t aq[4][4];

    for (int j = 0; j < nkv; j++) {
        __syncthreads();
        if (j + 1 < nkv) issue_kv(j + 1);
        CP_COMMIT();
        CP_WAIT(1);
        __syncthreads();

        if (j == 0) {
#pragma unroll
            for (int ks = 0; ks < 4; ks++) {
                uint32_t addr = qb + (uint32_t)((w * 16 + (lane & 15)) * FRS)
                              + ks * 32 + ((lane >> 4) << 4);
                ldm_x4(aq[ks], addr);
            }
        }

        uint32_t kb = sbase + FQ_BYTES + (j & 1) * FSTAGE;
        uint32_t vb = kb + FKV_BYTES;

        float sacc[8][4];
#pragma unroll
        for (int nt = 0; nt < 8; nt++)
#pragma unroll
            for (int e = 0; e < 4; e++) sacc[nt][e] = 0.f;

#pragma unroll
        for (int ks = 0; ks < 4; ks++) {
            uint32_t bf[8][2];
#pragma unroll
            for (int p = 0; p < 4; p++) {
                uint32_t r4[4];
                uint32_t addr = kb + (uint32_t)((p * 16 + (lane & 7) + ((lane >> 4) << 3)) * FRS)
                              + ks * 32 + (((lane >> 3) & 1) << 4);
                ldm_x4(r4, addr);
                bf[2 * p][0] = r4[0]; bf[2 * p][1] = r4[1];
                bf[2 * p + 1][0] = r4[2]; bf[2 * p + 1][1] = r4[3];
            }
#pragma unroll
            for (int nt = 0; nt < 8; nt++)
                mma16816(sacc[nt], aq[ks], bf[nt]);
        }

        int j0 = j * 64;
        int rowg0 = q0 + w * 16 + qq;
        int rowg1 = rowg0 + 8;
        bool needmask = (j >= nkv - 2);

        float rm0 = -1e30f, rm1 = -1e30f;
#pragma unroll
        for (int nt = 0; nt < 8; nt++) {
            int cb = j0 + nt * 8 + rr * 2;
            float s0 = sacc[nt][0] * 0.125f;
            float s1 = sacc[nt][1] * 0.125f;
            float s2 = sacc[nt][2] * 0.125f;
            float s3 = sacc[nt][3] * 0.125f;
            if (needmask) {
                if (cb     > rowg0) s0 = -1e30f;
                if (cb + 1 > rowg0) s1 = -1e30f;
                if (cb     > rowg1) s2 = -1e30f;
                if (cb + 1 > rowg1) s3 = -1e30f;
            }
            sacc[nt][0] = s0; sacc[nt][1] = s1; sacc[nt][2] = s2; sacc[nt][3] = s3;
            rm0 = fmaxf(rm0, fmaxf(s0, s1));
            rm1 = fmaxf(rm1, fmaxf(s2, s3));
        }
#pragma unroll
        for (int od = 1; od <= 2; od <<= 1) {
            rm0 = fmaxf(rm0, __shfl_xor_sync(0xffffffffu, rm0, od));
            rm1 = fmaxf(rm1, __shfl_xor_sync(0xffffffffu, rm1, od));
        }
        float mn0 = fmaxf(m0, rm0), mn1 = fmaxf(m1, rm1);
        float c0 = __expf(m0 - mn0), c1 = __expf(m1 - mn1);

        float rs0 = 0.f, rs1 = 0.f;
#pragma unroll
        for (int nt = 0; nt < 8; nt++) {
            float p0 = __expf(sacc[nt][0] - mn0);
            float p1 = __expf(sacc[nt][1] - mn0);
            float p2 = __expf(sacc[nt][2] - mn1);
            float p3 = __expf(sacc[nt][3] - mn1);
            sacc[nt][0] = p0; sacc[nt][1] = p1; sacc[nt][2] = p2; sacc[nt][3] = p3;
            rs0 += p0 + p1; rs1 += p2 + p3;
        }
#pragma unroll
        for (int od = 1; od <= 2; od <<= 1) {
            rs0 += __shfl_xor_sync(0xffffffffu, rs0, od);
            rs1 += __shfl_xor_sync(0xffffffffu, rs1, od);
        }
        l0 = l0 * c0 + rs0;
        l1 = l1 * c1 + rs1;
        m0 = mn0; m1 = mn1;

#pragma unroll
        for (int nt = 0; nt < 8; nt++) {
            o[nt][0] *= c0; o[nt][1] *= c0;
            o[nt][2] *= c1; o[nt][3] *= c1;
        }

        uint32_t ap[4][4];
#pragma unroll
        for (int ks2 = 0; ks2 < 4; ks2++) {
            ap[ks2][0] = pack_h2(sacc[2 * ks2][0],     sacc[2 * ks2][1]);
            ap[ks2][1] = pack_h2(sacc[2 * ks2][2],     sacc[2 * ks2][3]);
            ap[ks2][2] = pack_h2(sacc[2 * ks2 + 1][0], sacc[2 * ks2 + 1][1]);
            ap[ks2][3] = pack_h2(sacc[2 * ks2 + 1][2], sacc[2 * ks2 + 1][3]);
        }

#pragma unroll
        for (int ks2 = 0; ks2 < 4; ks2++) {
            uint32_t bf[8][2];
#pragma unroll
            for (int p = 0; p < 4; p++) {
                uint32_t r4[4];
                uint32_t addr = vb + (uint32_t)((p * 16 + (lane & 7) + ((lane >> 4) << 3)) * FRS)
                              + ks2 * 32 + (((lane >> 3) & 1) << 4);
                ldm_x4(r4, addr);
                bf[2 * p][0] = r4[0]; bf[2 * p][1] = r4[1];
                bf[2 * p + 1][0] = r4[2]; bf[2 * p + 1][1] = r4[3];
            }
#pragma unroll
            for (int nt = 0; nt < 8; nt++)
                mma16816(o[nt], ap[ks2], bf[nt]);
        }
    }

    float inv0 = 1.f / l0, inv1 = 1.f / l1;
    long obase = ((long)b * T_ + q0 + w * 16) * D_ + h * HD_;
#pragma unroll
    for (int nt = 0; nt < 8; nt++) {
        int col = nt * 8 + rr * 2;
        *(__half2*)&Og[obase + (long)qq * D_ + col] =
            __floats2half2_rn(o[nt][0] * inv0, o[nt][1] * inv0);
        *(__half2*)&Og[obase + (long)(qq + 8) * D_ + col] =
            __floats2half2_rn(o[nt][2] * inv1, o[nt][3] * inv1);
    }
}

// ---------------- single transpose ----------------
__global__ void transpose_kernel(const float* __restrict__ in, __half* __restrict__ out,
                                 int Kd, int Nd, int Nout, long sIn, long sOut)
{
    __shared__ float t[32][33];
    int zz = blockIdx.z;
    in  += (long)zz * sIn;
    out += (long)zz * sOut;
    int n = blockIdx.x * 32 + threadIdx.x;
#pragma unroll
    for (int j = 0; j < 4; j++) {
        int k = blockIdx.y * 32 + threadIdx.y + j * 8;
        t[threadIdx.y + j * 8][threadIdx.x] = (n < Nd && k < Kd) ? in[(long)k * Nd + n] : 0.f;
    }
    __syncthreads();
#pragma unroll
    for (int j = 0; j < 4; j++) {
        int n2 = blockIdx.x * 32 + threadIdx.y + j * 8;
        int k2 = blockIdx.y * 32 + threadIdx.x;
        if (n2 < Nout && k2 < Kd) out[(long)n2 * Kd + k2] = __float2half(t[threadIdx.x][threadIdx.y + j * 8]);
    }
}

// ---------------- merged 4x D×D transpose ----------------
__global__ void transpose4_kernel(const float* __restrict__ wq, const float* __restrict__ wk,
                                  const float* __restrict__ wv, const float* __restrict__ wp,
                                  __half* __restrict__ qkvT, __half* __restrict__ wpT)
{
    __shared__ float t[32][33];
    int zz = blockIdx.z;
    int which = zz & 3, l = zz >> 2;
    const float* in;
    __half* out;
    if (which == 0)      { in = wq + (long)l * D_ * D_; out = qkvT + (long)l * 3 * D_ * D_; }
    else if (which == 1) { in = wk + (long)l * D_ * D_; out = qkvT + (long)l * 3 * D_ * D_ + (long)D_ * D_; }
    else if (which == 2) { in = wv + (long)l * D_ * D_; out = qkvT + (long)l * 3 * D_ * D_ + 2L * D_ * D_; }
    else                 { in = wp + (long)l * D_ * D_; out = wpT  + (long)l * D_ * D_; }

    int n = blockIdx.x * 32 + threadIdx.x;
#pragma unroll
    for (int j = 0; j < 4; j++) {
        int k = blockIdx.y * 32 + threadIdx.y + j * 8;
        t[threadIdx.y + j * 8][threadIdx.x] = in[(long)k * D_ + n];
    }
    __syncthreads();
#pragma unroll
    for (int j = 0; j < 4; j++) {
        int n2 = blockIdx.x * 32 + threadIdx.y + j * 8;
        int k2 = blockIdx.y * 32 + threadIdx.x;
        out[(long)n2 * D_ + k2] = __float2half(t[threadIdx.x][threadIdx.y + j * 8]);
    }
}

// ---------------- embedding ----------------
__global__ void embed_kernel(const int* __restrict__ idx, const float* __restrict__ tok,
                             const float* __restrict__ pos, float* __restrict__ x)
{
    long i = (long)blockIdx.x * 256 + threadIdx.x;
    if (i >= (long)NT * D_) return;
    int d = (int)(i % D_);
    long row = i / D_;
    int t = (int)(row % T_);
    x[i] = tok[(long)idx[row] * D_ + d] + pos[(long)t * D_ + d];
}

// ---------------- layernorm ----------------
__global__ void layernorm_kernel(const float* __restrict__ x, const float* __restrict__ w,
                                 const float* __restrict__ b, __half* __restrict__ y)
{
    int r = blockIdx.x;
    const float* xr = x + (long)r * D_;
    __half* yr = y + (long)r * D_;
    __shared__ float s1[256], s2[256];
    int tid = threadIdx.x;
    float a = 0.f, sq = 0.f;
    for (int i = tid; i < D_; i += 256) { float v = xr[i]; a += v; sq += v * v; }
    s1[tid] = a; s2[tid] = sq; __syncthreads();
    for (int s = 128; s > 0; s >>= 1) {
        if (tid < s) { s1[tid] += s1[tid + s]; s2[tid] += s2[tid + s]; }
        __syncthreads();
    }
    float mu = s1[0] * (1.f / D_);
    float var = s2[0] * (1.f / D_) - mu * mu;
    float rstd = rsqrtf(var + 1e-5f);
    for (int i = tid; i < D_; i += 256)
        yr[i] = __float2half((xr[i] - mu) * rstd * w[i] + b[i]);
}

// ---------------- NLL from partials ----------------
__global__ void nll_from_partials(const float2* __restrict__ NP, const float* __restrict__ logits,
                                  const int* __restrict__ targets, float* __restrict__ nll)
{
    int row = blockIdx.x;
    const float2* p = NP + (long)row * NPART;
    int tid = threadIdx.x;
    float m = -1e30f, s = 0.f;
    for (int i = tid; i < NPART; i += 256) {
        float2 v = p[i];
        float mn = fmaxf(m, v.x);
        s = s * fexp(m - mn) + v.y * fexp(v.x - mn);
        m = mn;
    }
#pragma unroll
    for (int o = 16; o; o >>= 1) {
        float mo = __shfl_xor_sync(0xffffffffu, m, o);
        float so = __shfl_xor_sync(0xffffffffu, s, o);
        float mn = fmaxf(m, mo);
        s = s * fexp(m - mn) + so * fexp(mo - mn);
        m = mn;
    }
    __shared__ float sm[8], ssh[8];
    if ((tid & 31) == 0) { sm[tid >> 5] = m; ssh[tid >> 5] = s; }
    __syncthreads();
    if (tid == 0) {
        m = sm[0]; s = ssh[0];
#pragma unroll
        for (int i = 1; i < 8; i++) {
            float mn = fmaxf(m, sm[i]);
            s = s * fexp(m - mn) + ssh[i] * fexp(sm[i] - mn);
            m = mn;
        }
        nll[row] = m + logf(s) - logits[(long)row * V_ + targets[row]];
    }
}

__global__ void loss_reduce_kernel(const float* __restrict__ nll, float* __restrict__ out)
{
    __shared__ float red[256];
    int tid = threadIdx.x;
    float a = 0.f;
    for (int i = tid; i < NT; i += 256) a += nll[i];
    red[tid] = a; __syncthreads();
    for (int s = 128; s > 0; s >>= 1) { if (tid < s) red[tid] += red[tid + s]; __syncthreads(); }
    if (tid == 0) out[0] = red[0] * (1.f / NT);
}

// ---------------- host ----------------
#define SMEM128 81920

extern "C" void kernel_launch(void* const* d_in, const int* in_sizes, int n_in,
                              void* d_out, int out_size)
{
    const float* tok_emb = (const float*)d_in[0];
    const float* pos_emb = (const float*)d_in[1];
    const float* ln1_w   = (const float*)d_in[2];
    const float* ln1_b   = (const float*)d_in[3];
    const float* ln2_w   = (const float*)d_in[4];
    const float* ln2_b   = (const float*)d_in[5];
    const float* wq      = (const float*)d_in[6];
    const float* wk      = (const float*)d_in[7];
    const float* wv      = (const float*)d_in[8];
    const float* wproj   = (const float*)d_in[9];
    const float* bproj   = (const float*)d_in[10];
    const float* w1      = (const float*)d_in[11];
    const float* b1      = (const float*)d_in[12];
    const float* w2      = (const float*)d_in[13];
    const float* b2      = (const float*)d_in[14];
    const float* lnf_w   = (const float*)d_in[15];
    const float* lnf_b   = (const float*)d_in[16];
    const float* lm_w    = (const float*)d_in[17];
    const float* lm_b    = (const float*)d_in[18];
    const int*   indexp  = (const int*)d_in[19];
    const int*   targets = (const int*)d_in[20];

    float* out = (float*)d_out;

    cudaFuncSetAttribute(gemm_h_kernel<128, float>,  cudaFuncAttributeMaxDynamicSharedMemorySize, SMEM128);
    cudaFuncSetAttribute(gemm_h_kernel<128, __half>, cudaFuncAttributeMaxDynamicSharedMemorySize, SMEM128);
    cudaFuncSetAttribute(flash_kernel, cudaFuncAttributeMaxDynamicSharedMemorySize, FSMEM);

    float *x, *nll;
    float2* npart;
    __half *h, *q, *kh, *vt, *att, *mlp;
    __half *qkvT, *wpT, *w1T, *w2T, *lmwT;
    cudaGetSymbolAddress((void**)&x,      g_x);
    cudaGetSymbolAddress((void**)&nll,    g_nll);
    cudaGetSymbolAddress((void**)&npart,  g_nllpart);
    cudaGetSymbolAddress((void**)&h,      g_h);
    cudaGetSymbolAddress((void**)&q,      g_q);
    cudaGetSymbolAddress((void**)&kh,     g_k);
    cudaGetSymbolAddress((void**)&vt,     g_vt);
    cudaGetSymbolAddress((void**)&att,    g_att);
    cudaGetSymbolAddress((void**)&mlp,    g_mlp);
    cudaGetSymbolAddress((void**)&qkvT,   g_wqkvT);
    cudaGetSymbolAddress((void**)&wpT,    g_wpT);
    cudaGetSymbolAddress((void**)&w1T,    g_w1T);
    cudaGetSymbolAddress((void**)&w2T,    g_w2T);
    cudaGetSymbolAddress((void**)&lmwT,   g_lmwT);

    dim3 tb(32, 8);

    {
        long total = (long)NT * D_;
        embed_kernel<<<(int)((total + 255) / 256), 256>>>(indexp, tok_emb, pos_emb, x);

        dim3 g4(D_ / 32, D_ / 32, 4 * L_);
        transpose4_kernel<<<g4, tb>>>(wq, wk, wv, wproj, qkvT, wpT);
        dim3 g1(FF / 32, D_ / 32, L_);
        transpose_kernel<<<g1, tb>>>(w1, w1T, D_, FF, FF, (long)D_ * FF, (long)FF * D_);
        dim3 g2(D_ / 32, FF / 32, L_);
        transpose_kernel<<<g2, tb>>>(w2, w2T, FF, D_, D_, (long)FF * D_, (long)D_ * FF);
    }

    for (int l = 0; l < L_; l++) {
        const __half* qkvT_l = qkvT + (long)l * 3 * D_ * D_;
        const __half* wpT_l  = wpT + (long)l * D_ * D_;
        const float*  bp_l   = bproj + (long)l * D_;
        const __half* w1T_l  = w1T + (long)l * FF * D_;
        const float*  b1_l   = b1 + (long)l * FF;
        const __half* w2T_l  = w2T + (long)l * D_ * FF;
        const float*  b2_l   = b2 + (long)l * D_;

        layernorm_kernel<<<NT, 256>>>(x, ln1_w + (long)l * D_, ln1_b + (long)l * D_, h);

        gemm_h_kernel<128, __half><<<dim3(3 * D_ / 128, NT / 128, 1), 256, SMEM128>>>(
            h, qkvT_l, nullptr, nullptr, q, kh, vt, nullptr, NT, 3 * D_, D_, D_, D_, D_,
            0, 0, 0, 0, 0, 0, 1, 1.f, 0, 2, 0);

        flash_kernel<<<dim3(T_ / 128, B_ * H_), 256, FSMEM>>>(q, kh, vt, att);

        gemm_h_kernel<128, float><<<dim3(D_ / 128, NT / 128, 1), 256, SMEM128>>>(
            att, wpT_l, bp_l, x, x, nullptr, nullptr, nullptr, NT, D_, D_, D_, D_, D_,
            0, 0, 0, 0, 0, 0, 1, 1.f, 0, 0, 0);

        layernorm_kernel<<<NT, 256>>>(x, ln2_w + (long)l * D_, ln2_b + (long)l * D_, h);

        gemm_h_kernel<128, __half><<<dim3(FF / 128, NT / 128, 1), 256, SMEM128>>>(
            h, w1T_l, b1_l, nullptr, mlp, nullptr, nullptr, nullptr, NT, FF, D_, D_, D_, FF,
            0, 0, 0, 0, 0, 0, 1, 1.f, 1, 0, 0);

        gemm_h_kernel<128, float><<<dim3(D_ / 128, NT / 128, 1), 256, SMEM128>>>(
            mlp, w2T_l, b2_l, x, x, nullptr, nullptr, nullptr, NT, D_, FF, FF, FF, D_,
            0, 0, 0, 0, 0, 0, 1, 1.f, 0, 0, 0);
    }

    layernorm_kernel<<<NT, 256>>>(x, lnf_w, lnf_b, h);

    long logits_elems = (long)NT * V_;
    if ((long)out_size >= logits_elems) {
        dim3 g3(VPAD / 32, D_ / 32, 1);
        transpose_kernel<<<g3, tb>>>(lm_w, lmwT, D_, V_, VPAD, 0, 0);

        gemm_h_kernel<128, float><<<dim3(NT / 128, VPAD / 128, 1), 256, SMEM128>>>(
            h, lmwT, lm_b, nullptr, out, nullptr, nullptr, npart, NT, V_, D_, D_, D_, V_,
            0, 0, 0, 0, 0, 0, 1, 1.f, 0, 0, 1);

        nll_from_partials<<<NT, 256>>>(npart, out, targets, nll);
        if ((long)out_size >= logits_elems + 1) {
            loss_reduce_kernel<<<1, 256>>>(nll, out + logits_elems);
        }
    }
}